// round 3
// baseline (speedup 1.0000x reference)
#include <cuda_runtime.h>
#include <cstdint>
#include <math.h>

#define N_  32
#define T_  1024
#define D_  512
#define H_  512
#define G4  2048

#define NB  128     // persistent CTAs (<= 148 SMs, all co-resident)
#define NTH 256
#define HSTR 516    // padded k-stride for smem tiles (bank stagger)

typedef unsigned long long ull;

// ---------------- packed f32x2 helpers ------------------------------------------
__device__ __forceinline__ void fma2(ull& d, const ull a, const ull b) {
    asm("fma.rn.f32x2 %0, %1, %2, %0;" : "+l"(d) : "l"(a), "l"(b));
}
__device__ __forceinline__ void add2(ull& d, const ull a) {
    asm("add.rn.f32x2 %0, %0, %1;" : "+l"(d) : "l"(a));
}
__device__ __forceinline__ ull bcast2(float x) {
    ull r; asm("mov.b64 %0, {%1, %1};" : "=l"(r) : "f"(x)); return r;
}
__device__ __forceinline__ float hsum2(ull a) {
    float lo, hi; asm("mov.b64 {%0, %1}, %2;" : "=f"(lo), "=f"(hi) : "l"(a));
    return lo + hi;
}

// ---------------- device scratch -------------------------------------------------
__device__ float g_xw[(size_t)N_ * T_ * G4];      // 256 MB: x@Wx + b, [(n*T+t)][2048]
__device__ float g_hbuf[2][N_][H_];               // double-buffered h, [n][k]
__device__ unsigned int g_count = 0;
__device__ volatile unsigned int g_gen = 0;

// ---------------- Phase 1: xw = x @ Wx + b  (32768 x 2048 x 512, FFMA2) ----------
__global__ __launch_bounds__(256, 2) void gemm_xw_kernel(const float* __restrict__ x,
                                                         const float* __restrict__ Wx,
                                                         const float* __restrict__ bias)
{
    __shared__ float As[8][128];   // A tile transposed: As[k][m]
    __shared__ float Bs[8][128];   // B tile: Bs[k][n]
    const int tid = threadIdx.x;
    const int bm = blockIdx.y, bn = blockIdx.x;
    const int tx = tid & 15, ty = tid >> 4;          // 16x16 thread grid, 8x8 microtile
    const int a_row = tid >> 1, a_k = (tid & 1) << 2;
    const int b_row = tid >> 5, b_col = (tid & 31) << 2;

    const float* xA = x + (size_t)(bm * 128 + a_row) * D_ + a_k;
    const float* wB = Wx + (size_t)b_row * G4 + bn * 128 + b_col;

    ull accp[8][4];                // acc[i][j pair], j packed in f32x2
#pragma unroll
    for (int i = 0; i < 8; i++)
#pragma unroll
        for (int j = 0; j < 4; j++) accp[i][j] = 0ULL;

    for (int k0 = 0; k0 < D_; k0 += 8) {
        float4 av = *(const float4*)(xA + k0);
        float4 bv = *(const float4*)(wB + (size_t)k0 * G4);
        __syncthreads();
        As[a_k + 0][a_row] = av.x;
        As[a_k + 1][a_row] = av.y;
        As[a_k + 2][a_row] = av.z;
        As[a_k + 3][a_row] = av.w;
        *(float4*)&Bs[b_row][b_col] = bv;
        __syncthreads();
#pragma unroll
        for (int kk = 0; kk < 8; kk++) {
            float a0[8];
            *(float4*)(a0)     = *(const float4*)&As[kk][ty * 8];
            *(float4*)(a0 + 4) = *(const float4*)&As[kk][ty * 8 + 4];
            ulonglong2 q0 = *(const ulonglong2*)&Bs[kk][tx * 8];
            ulonglong2 q1 = *(const ulonglong2*)&Bs[kk][tx * 8 + 4];
            ull b2[4] = {q0.x, q0.y, q1.x, q1.y};
            ull a2[8];
#pragma unroll
            for (int i = 0; i < 8; i++) a2[i] = bcast2(a0[i]);
#pragma unroll
            for (int i = 0; i < 8; i++)
#pragma unroll
                for (int j = 0; j < 4; j++)
                    fma2(accp[i][j], a2[i], b2[j]);
        }
    }

    ulonglong2 bq0 = *(const ulonglong2*)(bias + bn * 128 + tx * 8);
    ulonglong2 bq1 = *(const ulonglong2*)(bias + bn * 128 + tx * 8 + 4);
    ull bb2[4] = {bq0.x, bq0.y, bq1.x, bq1.y};
#pragma unroll
    for (int i = 0; i < 8; i++) {
#pragma unroll
        for (int j = 0; j < 4; j++) add2(accp[i][j], bb2[j]);
        size_t row = (size_t)(bm * 128 + ty * 8 + i);
        ulonglong2 s0, s1;
        s0.x = accp[i][0]; s0.y = accp[i][1];
        s1.x = accp[i][2]; s1.y = accp[i][3];
        *(ulonglong2*)(g_xw + row * G4 + bn * 128 + tx * 8)     = s0;
        *(ulonglong2*)(g_xw + row * G4 + bn * 128 + tx * 8 + 4) = s1;
    }
}

// ---------------- Phase 2: persistent recurrent kernel ---------------------------
__device__ __forceinline__ void gridbar()
{
    __syncthreads();
    if (threadIdx.x == 0) {
        __threadfence();                       // release: flush my writes
        unsigned gen = g_gen;
        if (atomicAdd(&g_count, 1) == NB - 1) {
            atomicExch(&g_count, 0);
            __threadfence();
            g_gen = gen + 1;
        } else {
            while (g_gen == gen) { }
            __threadfence();                   // acquire
        }
    }
    __syncthreads();
}

extern __shared__ float smem_dyn[];

__global__ __launch_bounds__(NTH, 1) void lstm_rec_kernel(const float* __restrict__ h0,
                                                          const float* __restrict__ Wh,
                                                          float* __restrict__ out)
{
    // smem layout (floats): Whs[16][HSTR] | hs[32][HSTR] | ap[8][32][16] | af[32][16] | cs[128]
    float* Whs = smem_dyn;                 // 16 * 516
    float* hs  = Whs + 16 * HSTR;          // 32 * 516
    float* ap  = hs + 32 * HSTR;           // 4096
    float* af  = ap + 8 * 32 * 16;         // 512
    float* cs  = af + 32 * 16;             // 128

    const int b   = blockIdx.x;
    const int tid = threadIdx.x;
    const int j0  = b * 4;                 // this CTA's 4 h-columns: j0..j0+3

    // Load weight slice transposed: Whs[c][k] = Wh[k][gate*512 + j0 + jj], c = gate*4+jj
    for (int idx = tid; idx < 16 * 512; idx += NTH) {
        int k = idx >> 4, c = idx & 15;
        int gate = c >> 2, jj = c & 3;
        Whs[c * HSTR + k] = Wh[(size_t)k * G4 + gate * H_ + j0 + jj];
    }
    if (tid < 128) {
        cs[tid] = 0.f;                     // c0 = 0,  cs[n*4+jj]
        int n = tid >> 2, jj = tid & 3;
        g_hbuf[0][n][j0 + jj] = h0[(size_t)n * H_ + j0 + jj];
    }
    gridbar();

    // mapping: warp = K-group (slice of 64 k's); lane covers 4n x 4c
    const int grp  = tid >> 5;             // 0..7
    const int lane = tid & 31;
    const int kbeg = grp * 64;
    const int n0   = lane >> 2;            // rows n0, n0+8, n0+16, n0+24
    const int c0r  = lane & 3;             // cols c0r, c0r+4, c0r+8, c0r+12 (jj=c0r, gate=cm)
    const int sub  = lane >> 3;            // staging: row within group of 4
    const int qo   = (lane & 7) * 8;       // staging: float offset within 64-float slice

    for (int t = 0; t < T_; t++) {
        // prefetch this thread's xw row early (hidden behind the GEMM)
        float4 xwv = make_float4(0.f, 0.f, 0.f, 0.f);
        if (tid < 128) {
            int n = tid >> 2, q = tid & 3;
            xwv = __ldcg((const float4*)(g_xw + ((size_t)n * T_ + t) * G4 + q * H_ + j0));
        }

        // stage this warp's own K-slice of h ([n][k] layout), coalesced 256B rows
        const float* hb = &g_hbuf[t & 1][0][0];
#pragma unroll
        for (int r = 0; r < 8; r++) {
            int row = r * 4 + sub;
            const float* src = hb + row * 512 + kbeg + qo;
            float4 va = __ldcg((const float4*)src);
            float4 vb = __ldcg((const float4*)(src + 4));
            float* dst = hs + row * HSTR + kbeg + qo;
            *(float4*)dst = va;
            *(float4*)(dst + 4) = vb;
        }
        __syncwarp();

        // partial GEMM over own K slice; K packed into f32x2 halves (even/odd sums)
        ull acc[4][4];
#pragma unroll
        for (int m = 0; m < 4; m++)
#pragma unroll
            for (int cm = 0; cm < 4; cm++) acc[m][cm] = 0ULL;

        const float* hpb = hs + kbeg;
        const float* wpb = Whs + kbeg;
#pragma unroll 4
        for (int kq = 0; kq < 16; kq++) {
            ulonglong2 hv[4], wv[4];
#pragma unroll
            for (int m = 0; m < 4; m++)
                hv[m] = *(const ulonglong2*)(hpb + (n0 + 8 * m) * HSTR + kq * 4);
#pragma unroll
            for (int cm = 0; cm < 4; cm++)
                wv[cm] = *(const ulonglong2*)(wpb + (cm * 4 + c0r) * HSTR + kq * 4);
#pragma unroll
            for (int m = 0; m < 4; m++)
#pragma unroll
                for (int cm = 0; cm < 4; cm++) {
                    fma2(acc[m][cm], hv[m].x, wv[cm].x);
                    fma2(acc[m][cm], hv[m].y, wv[cm].y);
                }
        }
#pragma unroll
        for (int m = 0; m < 4; m++)
#pragma unroll
            for (int cm = 0; cm < 4; cm++)
                ap[(grp * 32 + n0 + 8 * m) * 16 + cm * 4 + c0r] = hsum2(acc[m][cm]);
        __syncthreads();

        // reduce 8 partials + xw (prefetched)
        if (tid < 128) {
            int n = tid >> 2, q = tid & 3;
            float4 s = xwv;
#pragma unroll
            for (int g = 0; g < 8; g++) {
                float4 p = *(const float4*)(ap + (g * 32 + n) * 16 + q * 4);
                s.x += p.x; s.y += p.y; s.z += p.z; s.w += p.w;
            }
            *(float4*)(af + n * 16 + q * 4) = s;
        }
        __syncthreads();

        // gates + state update
        if (tid < 128) {
            int n = tid >> 2, jj = tid & 3;
            float ai  = af[n * 16 + 0  + jj];
            float afv = af[n * 16 + 4  + jj];
            float ao  = af[n * 16 + 8  + jj];
            float ag  = af[n * 16 + 12 + jj];
            float ig = 1.f / (1.f + expf(-ai));
            float fg = 1.f / (1.f + expf(-afv));
            float og = 1.f / (1.f + expf(-ao));
            float gg = tanhf(ag);
            float cn = fg * cs[tid] + ig * gg;
            cs[tid] = cn;
            float hn = og * tanhf(cn);
            g_hbuf[(t + 1) & 1][n][j0 + jj] = hn;
            out[((size_t)n * T_ + t) * H_ + j0 + jj] = hn;
        }
        gridbar();
    }
}

// ---------------- launch ----------------------------------------------------------
extern "C" void kernel_launch(void* const* d_in, const int* in_sizes, int n_in,
                              void* d_out, int out_size)
{
    const float* x    = (const float*)d_in[0];
    const float* h0   = (const float*)d_in[1];
    const float* Wx   = (const float*)d_in[2];
    const float* Wh   = (const float*)d_in[3];
    const float* bias = (const float*)d_in[4];
    float* out = (float*)d_out;

    dim3 g1(G4 / 128, (N_ * T_) / 128);
    gemm_xw_kernel<<<g1, 256>>>(x, Wx, bias);

    const int shmem = (16 * HSTR + 32 * HSTR + 8 * 32 * 16 + 32 * 16 + 128) * (int)sizeof(float);
    cudaFuncSetAttribute(lstm_rec_kernel, cudaFuncAttributeMaxDynamicSharedMemorySize, shmem);
    lstm_rec_kernel<<<NB, NTH, shmem>>>(h0, Wh, out);
}

// round 4
// speedup vs baseline: 1.0058x; 1.0058x over previous
#include <cuda_runtime.h>
#include <cstdint>
#include <math.h>

#define N_  32
#define T_  1024
#define D_  512
#define H_  512
#define G4  2048

#define NB  128     // persistent CTAs (<= 148 SMs, all co-resident)
#define NTH 256
#define HSTR 516    // padded k-stride for smem tiles (bank stagger)

typedef unsigned long long ull;

// ---------------- packed f32x2 helpers ------------------------------------------
__device__ __forceinline__ void fma2(ull& d, const ull a, const ull b) {
    asm("fma.rn.f32x2 %0, %1, %2, %0;" : "+l"(d) : "l"(a), "l"(b));
}
__device__ __forceinline__ void add2(ull& d, const ull a) {
    asm("add.rn.f32x2 %0, %0, %1;" : "+l"(d) : "l"(a));
}
__device__ __forceinline__ ull bcast2(float x) {
    ull r; asm("mov.b64 %0, {%1, %1};" : "=l"(r) : "f"(x)); return r;
}
__device__ __forceinline__ float hsum2(ull a) {
    float lo, hi; asm("mov.b64 {%0, %1}, %2;" : "=f"(lo), "=f"(hi) : "l"(a));
    return lo + hi;
}

// ---------------- device scratch -------------------------------------------------
__device__ float g_xw[(size_t)N_ * T_ * G4];      // 256 MB: x@Wx + b, [(n*T+t)][2048]
__device__ float g_hbuf[2][N_][H_];               // double-buffered h, [n][k]
__device__ unsigned int g_grp[16 * 64];           // 16 group counters, 256B apart
__device__ unsigned int g_root = 0;
__device__ volatile unsigned int g_gen = 0;

// ---------------- barrier state reset (runs before the persistent kernel) --------
__global__ void reset_barrier_kernel()
{
    int i = threadIdx.x;
    if (i < 16) g_grp[i * 64] = 0u;
    if (i == 16) g_root = 0u;
    if (i == 17) g_gen = 0u;
}

// ---------------- Phase 1: xw = x @ Wx + b  (32768 x 2048 x 512, FFMA2) ----------
__global__ __launch_bounds__(256, 2) void gemm_xw_kernel(const float* __restrict__ x,
                                                         const float* __restrict__ Wx,
                                                         const float* __restrict__ bias)
{
    __shared__ float As[8][128];   // A tile transposed: As[k][m]
    __shared__ float Bs[8][128];   // B tile: Bs[k][n]
    const int tid = threadIdx.x;
    const int bm = blockIdx.y, bn = blockIdx.x;
    const int tx = tid & 15, ty = tid >> 4;          // 16x16 thread grid, 8x8 microtile
    const int a_row = tid >> 1, a_k = (tid & 1) << 2;
    const int b_row = tid >> 5, b_col = (tid & 31) << 2;

    const float* xA = x + (size_t)(bm * 128 + a_row) * D_ + a_k;
    const float* wB = Wx + (size_t)b_row * G4 + bn * 128 + b_col;

    ull accp[8][4];
#pragma unroll
    for (int i = 0; i < 8; i++)
#pragma unroll
        for (int j = 0; j < 4; j++) accp[i][j] = 0ULL;

    for (int k0 = 0; k0 < D_; k0 += 8) {
        float4 av = *(const float4*)(xA + k0);
        float4 bv = *(const float4*)(wB + (size_t)k0 * G4);
        __syncthreads();
        As[a_k + 0][a_row] = av.x;
        As[a_k + 1][a_row] = av.y;
        As[a_k + 2][a_row] = av.z;
        As[a_k + 3][a_row] = av.w;
        *(float4*)&Bs[b_row][b_col] = bv;
        __syncthreads();
#pragma unroll
        for (int kk = 0; kk < 8; kk++) {
            float a0[8];
            *(float4*)(a0)     = *(const float4*)&As[kk][ty * 8];
            *(float4*)(a0 + 4) = *(const float4*)&As[kk][ty * 8 + 4];
            ulonglong2 q0 = *(const ulonglong2*)&Bs[kk][tx * 8];
            ulonglong2 q1 = *(const ulonglong2*)&Bs[kk][tx * 8 + 4];
            ull b2[4] = {q0.x, q0.y, q1.x, q1.y};
            ull a2[8];
#pragma unroll
            for (int i = 0; i < 8; i++) a2[i] = bcast2(a0[i]);
#pragma unroll
            for (int i = 0; i < 8; i++)
#pragma unroll
                for (int j = 0; j < 4; j++)
                    fma2(accp[i][j], a2[i], b2[j]);
        }
    }

    ulonglong2 bq0 = *(const ulonglong2*)(bias + bn * 128 + tx * 8);
    ulonglong2 bq1 = *(const ulonglong2*)(bias + bn * 128 + tx * 8 + 4);
    ull bb2[4] = {bq0.x, bq0.y, bq1.x, bq1.y};
#pragma unroll
    for (int i = 0; i < 8; i++) {
#pragma unroll
        for (int j = 0; j < 4; j++) add2(accp[i][j], bb2[j]);
        size_t row = (size_t)(bm * 128 + ty * 8 + i);
        ulonglong2 s0, s1;
        s0.x = accp[i][0]; s0.y = accp[i][1];
        s1.x = accp[i][2]; s1.y = accp[i][3];
        *(ulonglong2*)(g_xw + row * G4 + bn * 128 + tx * 8)     = s0;
        *(ulonglong2*)(g_xw + row * G4 + bn * 128 + tx * 8 + 4) = s1;
    }
}

// ---------------- Phase 2: persistent recurrent kernel ---------------------------
// Two-level tree barrier: 16 groups x 8 CTAs, monotonic counters (no resets).
__device__ __forceinline__ void gridbar(int b, unsigned s)
{
    __syncthreads();
    if (threadIdx.x == 0) {
        __threadfence();                       // release: flush my h writes
        unsigned old = atomicAdd(&g_grp[(b >> 3) * 64], 1u);
        if (old == 8u * s - 1u) {              // last arriver in my group
            unsigned r = atomicAdd(&g_root, 1u);
            if (r == 16u * s - 1u) {           // last group overall
                __threadfence();
                g_gen = s;
            }
        }
        while (g_gen < s) { }
        __threadfence();                       // acquire: invalidate L1 before reads
    }
    __syncthreads();
}

extern __shared__ float smem_dyn[];

__global__ __launch_bounds__(NTH, 1) void lstm_rec_kernel(const float* __restrict__ h0,
                                                          const float* __restrict__ Wh,
                                                          float* __restrict__ out)
{
    // smem layout (floats): Whs[16][HSTR] | hs[32][HSTR] | ap[8][32][16] | af[32][16] | cs[128]
    float* Whs = smem_dyn;                 // 16 * 516
    float* hs  = Whs + 16 * HSTR;          // 32 * 516
    float* ap  = hs + 32 * HSTR;           // 4096
    float* af  = ap + 8 * 32 * 16;         // 512
    float* cs  = af + 32 * 16;             // 128

    const int b   = blockIdx.x;
    const int tid = threadIdx.x;
    const int j0  = b * 4;                 // this CTA's 4 h-columns: j0..j0+3

    // Load weight slice transposed: Whs[c][k] = Wh[k][gate*512 + j0 + jj], c = gate*4+jj
    for (int idx = tid; idx < 16 * 512; idx += NTH) {
        int k = idx >> 4, c = idx & 15;
        int gate = c >> 2, jj = c & 3;
        Whs[c * HSTR + k] = Wh[(size_t)k * G4 + gate * H_ + j0 + jj];
    }
    if (tid < 128) {
        cs[tid] = 0.f;                     // c0 = 0,  cs[n*4+jj]
        int n = tid >> 2, jj = tid & 3;
        g_hbuf[0][n][j0 + jj] = h0[(size_t)n * H_ + j0 + jj];
    }
    unsigned step = 1;
    gridbar(b, step); step++;

    // mapping: warp = K-group (slice of 64 k's); lane covers 4n x 4c
    const int grp  = tid >> 5;             // 0..7
    const int lane = tid & 31;
    const int kbeg = grp * 64;
    const int n0   = lane >> 2;            // rows n0, n0+8, n0+16, n0+24
    const int c0r  = lane & 3;             // cols c0r, c0r+4, c0r+8, c0r+12
    const int sub  = lane >> 3;            // staging: row within group of 4
    const int qo   = (lane & 7) * 8;       // staging: float offset within 64-float slice

    for (int t = 0; t < T_; t++) {
        // prefetch this thread's xw row early (hidden behind the GEMM)
        float4 xwv = make_float4(0.f, 0.f, 0.f, 0.f);
        if (tid < 128) {
            int n = tid >> 2, q = tid & 3;
            xwv = __ldcg((const float4*)(g_xw + ((size_t)n * T_ + t) * G4 + q * H_ + j0));
        }

        // stage this warp's own K-slice of h ([n][k] layout), coalesced 256B rows
        const float* hb = &g_hbuf[t & 1][0][0];
#pragma unroll
        for (int r = 0; r < 8; r++) {
            int row = r * 4 + sub;
            const float* src = hb + row * 512 + kbeg + qo;
            float4 va = __ldcg((const float4*)src);
            float4 vb = __ldcg((const float4*)(src + 4));
            float* dst = hs + row * HSTR + kbeg + qo;
            *(float4*)dst = va;
            *(float4*)(dst + 4) = vb;
        }
        __syncwarp();

        // partial GEMM over own K slice; K packed into f32x2 halves (even/odd sums)
        ull acc[4][4];
#pragma unroll
        for (int m = 0; m < 4; m++)
#pragma unroll
            for (int cm = 0; cm < 4; cm++) acc[m][cm] = 0ULL;

        const float* hpb = hs + kbeg;
        const float* wpb = Whs + kbeg;
#pragma unroll 4
        for (int kq = 0; kq < 16; kq++) {
            ulonglong2 hv[4], wv[4];
#pragma unroll
            for (int m = 0; m < 4; m++)
                hv[m] = *(const ulonglong2*)(hpb + (n0 + 8 * m) * HSTR + kq * 4);
#pragma unroll
            for (int cm = 0; cm < 4; cm++)
                wv[cm] = *(const ulonglong2*)(wpb + (cm * 4 + c0r) * HSTR + kq * 4);
#pragma unroll
            for (int m = 0; m < 4; m++)
#pragma unroll
                for (int cm = 0; cm < 4; cm++) {
                    fma2(acc[m][cm], hv[m].x, wv[cm].x);
                    fma2(acc[m][cm], hv[m].y, wv[cm].y);
                }
        }
#pragma unroll
        for (int m = 0; m < 4; m++)
#pragma unroll
            for (int cm = 0; cm < 4; cm++)
                ap[(grp * 32 + n0 + 8 * m) * 16 + cm * 4 + c0r] = hsum2(acc[m][cm]);
        __syncthreads();

        // reduce 8 partials + xw (prefetched)
        if (tid < 128) {
            int n = tid >> 2, q = tid & 3;
            float4 s = xwv;
#pragma unroll
            for (int g = 0; g < 8; g++) {
                float4 p = *(const float4*)(ap + (g * 32 + n) * 16 + q * 4);
                s.x += p.x; s.y += p.y; s.z += p.z; s.w += p.w;
            }
            *(float4*)(af + n * 16 + q * 4) = s;
        }
        __syncthreads();

        // gates + state update
        if (tid < 128) {
            int n = tid >> 2, jj = tid & 3;
            float ai  = af[n * 16 + 0  + jj];
            float afv = af[n * 16 + 4  + jj];
            float ao  = af[n * 16 + 8  + jj];
            float ag  = af[n * 16 + 12 + jj];
            float ig = 1.f / (1.f + expf(-ai));
            float fg = 1.f / (1.f + expf(-afv));
            float og = 1.f / (1.f + expf(-ao));
            float gg = tanhf(ag);
            float cn = fg * cs[tid] + ig * gg;
            cs[tid] = cn;
            float hn = og * tanhf(cn);
            g_hbuf[(t + 1) & 1][n][j0 + jj] = hn;
            out[((size_t)n * T_ + t) * H_ + j0 + jj] = hn;
        }
        gridbar(b, step); step++;
    }
}

// ---------------- launch ----------------------------------------------------------
extern "C" void kernel_launch(void* const* d_in, const int* in_sizes, int n_in,
                              void* d_out, int out_size)
{
    const float* x    = (const float*)d_in[0];
    const float* h0   = (const float*)d_in[1];
    const float* Wx   = (const float*)d_in[2];
    const float* Wh   = (const float*)d_in[3];
    const float* bias = (const float*)d_in[4];
    float* out = (float*)d_out;

    reset_barrier_kernel<<<1, 32>>>();

    dim3 g1(G4 / 128, (N_ * T_) / 128);
    gemm_xw_kernel<<<g1, 256>>>(x, Wx, bias);

    const int shmem = (16 * HSTR + 32 * HSTR + 8 * 32 * 16 + 32 * 16 + 128) * (int)sizeof(float);
    cudaFuncSetAttribute(lstm_rec_kernel, cudaFuncAttributeMaxDynamicSharedMemorySize, shmem);
    lstm_rec_kernel<<<NB, NTH, shmem>>>(h0, Wh, out);
}

// round 5
// speedup vs baseline: 1.0307x; 1.0248x over previous
#include <cuda_runtime.h>
#include <cstdint>
#include <math.h>

#define N_  32
#define T_  1024
#define D_  512
#define H_  512
#define G4  2048

#define NB   128
#define NTH  512
#define APS  256     // ap plane stride (ull)

typedef unsigned long long ull;

__device__ __forceinline__ void fma2(ull& d, const ull a, const ull b) {
    asm("fma.rn.f32x2 %0, %1, %2, %0;" : "+l"(d) : "l"(a), "l"(b));
}
__device__ __forceinline__ void add2(ull& d, const ull a) {
    asm("add.rn.f32x2 %0, %0, %1;" : "+l"(d) : "l"(a));
}
__device__ __forceinline__ ull bcast2(float x) {
    ull r; asm("mov.b64 %0, {%1, %1};" : "=l"(r) : "f"(x)); return r;
}
__device__ __forceinline__ void unpack2(float& lo, float& hi, ull a) {
    asm("mov.b64 {%0, %1}, %2;" : "=f"(lo), "=f"(hi) : "l"(a));
}

// ---------------- device scratch -------------------------------------------------
__device__ float g_xw[(size_t)N_ * T_ * G4];   // x@Wx + b, [(n*T+t)][2048]
__device__ float g_hbuf[2][H_][N_];            // double-buffered h, [k][n] (128B rows)
__device__ unsigned int g_grp[16 * 64];        // 16 group counters, 256B apart
__device__ unsigned int g_root = 0;
__device__ volatile unsigned int g_gen = 0;

__global__ void reset_barrier_kernel()
{
    int i = threadIdx.x;
    if (i < 16) g_grp[i * 64] = 0u;
    if (i == 16) g_root = 0u;
    if (i == 17) g_gen = 0u;
}

// ---------------- Phase 1: xw = x @ Wx + b (unchanged, proven) --------------------
__global__ __launch_bounds__(256, 2) void gemm_xw_kernel(const float* __restrict__ x,
                                                         const float* __restrict__ Wx,
                                                         const float* __restrict__ bias)
{
    __shared__ float As[8][128];
    __shared__ float Bs[8][128];
    const int tid = threadIdx.x;
    const int bm = blockIdx.y, bn = blockIdx.x;
    const int tx = tid & 15, ty = tid >> 4;
    const int a_row = tid >> 1, a_k = (tid & 1) << 2;
    const int b_row = tid >> 5, b_col = (tid & 31) << 2;

    const float* xA = x + (size_t)(bm * 128 + a_row) * D_ + a_k;
    const float* wB = Wx + (size_t)b_row * G4 + bn * 128 + b_col;

    ull accp[8][4];
#pragma unroll
    for (int i = 0; i < 8; i++)
#pragma unroll
        for (int j = 0; j < 4; j++) accp[i][j] = 0ULL;

    for (int k0 = 0; k0 < D_; k0 += 8) {
        float4 av = *(const float4*)(xA + k0);
        float4 bv = *(const float4*)(wB + (size_t)k0 * G4);
        __syncthreads();
        As[a_k + 0][a_row] = av.x;
        As[a_k + 1][a_row] = av.y;
        As[a_k + 2][a_row] = av.z;
        As[a_k + 3][a_row] = av.w;
        *(float4*)&Bs[b_row][b_col] = bv;
        __syncthreads();
#pragma unroll
        for (int kk = 0; kk < 8; kk++) {
            float a0[8];
            *(float4*)(a0)     = *(const float4*)&As[kk][ty * 8];
            *(float4*)(a0 + 4) = *(const float4*)&As[kk][ty * 8 + 4];
            ulonglong2 q0 = *(const ulonglong2*)&Bs[kk][tx * 8];
            ulonglong2 q1 = *(const ulonglong2*)&Bs[kk][tx * 8 + 4];
            ull b2[4] = {q0.x, q0.y, q1.x, q1.y};
            ull a2[8];
#pragma unroll
            for (int i = 0; i < 8; i++) a2[i] = bcast2(a0[i]);
#pragma unroll
            for (int i = 0; i < 8; i++)
#pragma unroll
                for (int j = 0; j < 4; j++)
                    fma2(accp[i][j], a2[i], b2[j]);
        }
    }

    ulonglong2 bq0 = *(const ulonglong2*)(bias + bn * 128 + tx * 8);
    ulonglong2 bq1 = *(const ulonglong2*)(bias + bn * 128 + tx * 8 + 4);
    ull bb2[4] = {bq0.x, bq0.y, bq1.x, bq1.y};
#pragma unroll
    for (int i = 0; i < 8; i++) {
#pragma unroll
        for (int j = 0; j < 4; j++) add2(accp[i][j], bb2[j]);
        size_t row = (size_t)(bm * 128 + ty * 8 + i);
        ulonglong2 s0, s1;
        s0.x = accp[i][0]; s0.y = accp[i][1];
        s1.x = accp[i][2]; s1.y = accp[i][3];
        *(ulonglong2*)(g_xw + row * G4 + bn * 128 + tx * 8)     = s0;
        *(ulonglong2*)(g_xw + row * G4 + bn * 128 + tx * 8 + 4) = s1;
    }
}

// ---------------- Phase 2 --------------------------------------------------------
__device__ __forceinline__ void gridbar(int b, unsigned s)
{
    __syncthreads();
    if (threadIdx.x == 0) {
        __threadfence();
        unsigned old = atomicAdd(&g_grp[(b >> 3) * 64], 1u);
        if (old == 8u * s - 1u) {
            unsigned r = atomicAdd(&g_root, 1u);
            if (r == 16u * s - 1u) { __threadfence(); g_gen = s; }
        }
        while (g_gen < s) { }
        __threadfence();
    }
    __syncthreads();
}

extern __shared__ float smem_dyn[];

__global__ __launch_bounds__(NTH, 1) void lstm_rec_kernel(const float* __restrict__ h0,
                                                          const float* __restrict__ Wh,
                                                          float* __restrict__ out)
{
    // smem: ws[512][16] | hs[512][32] | ap ull[16][APS] | af[16][34] | cs[128]
    float* ws = smem_dyn;                     // 8192 floats
    float* hs = ws + 512 * 16;                // 16384 floats
    ull*   ap = (ull*)(hs + 512 * 32);        // 16*APS ull
    float* af = (float*)(ap + 16 * APS);      // 544 floats
    float* cs = af + 16 * 34;                 // 128 floats

    const int b   = blockIdx.x;
    const int tid = threadIdx.x;
    const int j0  = b * 4;

    // weights: ws[k][c], c = gate*4+jj
    for (int idx = tid; idx < 512 * 16; idx += NTH) {
        int k = idx >> 4, c = idx & 15;
        ws[idx] = Wh[(size_t)k * G4 + (c >> 2) * H_ + j0 + (c & 3)];
    }
    if (tid < 128) {
        cs[tid] = 0.f;
        int jj = tid >> 5, n = tid & 31;
        g_hbuf[0][j0 + jj][n] = h0[(size_t)n * H_ + j0 + jj];
    }
    unsigned step = 1;
    gridbar(b, step); step++;

    // GEMM mapping
    const int w    = tid >> 5;                 // warp 0..15, k in [w*32, w*32+32)
    const int lane = tid & 31;
    const int kg   = lane >> 4;                // intra-warp 2-way K split
    const int pos  = lane & 15;
    const int n0   = (pos & 3) * 8;            // 4 n-pairs: n0..n0+7
    const int cg4  = (pos >> 2) * 4;           // 4 c's: cg4..cg4+3
    const int kbase = w * 32 + kg * 16;

    // reduce ids (tid < 256): np = tid>>4, c = tid&15, output idx = tid
    const int rnp = tid >> 4, rc = tid & 15;

    for (int t = 0; t < T_; t++) {
        // xw prefetch (2 floats per reduce thread)
        float xw0 = 0.f, xw1 = 0.f;
        if (tid < 256) {
            size_t base = (size_t)(rc >> 2) * H_ + j0 + (rc & 3);
            xw0 = __ldcg(g_xw + ((size_t)(2 * rnp)     * T_ + t) * G4 + base);
            xw1 = __ldcg(g_xw + ((size_t)(2 * rnp + 1) * T_ + t) * G4 + base);
        }
        // stage h: g_hbuf[t&1][k][n] -> hs[k][n]
        const float* hb = &g_hbuf[t & 1][0][0];
#pragma unroll
        for (int j = 0; j < 8; j++) {
            int idx = tid + j * NTH;           // 4096 float4 chunks
            float4 v = __ldcg((const float4*)(hb + idx * 4));
            *(float4*)(hs + idx * 4) = v;
        }
        __syncthreads();

        // GEMM: acc[np 4][c 4], n-packed f32x2
        ull acc[4][4];
#pragma unroll
        for (int u = 0; u < 4; u++)
#pragma unroll
            for (int c = 0; c < 4; c++) acc[u][c] = 0ULL;

#pragma unroll
        for (int i = 0; i < 16; i++) {
            int k = kbase + i;
            const float* hr = hs + k * 32 + n0;
            ulonglong2 hA = *(const ulonglong2*)hr;
            ulonglong2 hB = *(const ulonglong2*)(hr + 4);
            ull hv[4] = {hA.x, hA.y, hB.x, hB.y};
            float4 wf = *(const float4*)(ws + k * 16 + cg4);
            ull wb[4] = {bcast2(wf.x), bcast2(wf.y), bcast2(wf.z), bcast2(wf.w)};
#pragma unroll
            for (int u = 0; u < 4; u++)
#pragma unroll
                for (int c = 0; c < 4; c++)
                    fma2(acc[u][c], hv[u], wb[c]);
        }
        // fold intra-warp K split
#pragma unroll
        for (int u = 0; u < 4; u++)
#pragma unroll
            for (int c = 0; c < 4; c++) {
                ull o = __shfl_xor_sync(0xFFFFFFFFu, acc[u][c], 16);
                add2(acc[u][c], o);
            }
        if (kg == 0) {
            ull* pl = ap + w * APS;
#pragma unroll
            for (int u = 0; u < 4; u++) {
                int np = (n0 >> 1) + u;
                ulonglong2 s0, s1;
                s0.x = acc[u][0]; s0.y = acc[u][1];
                s1.x = acc[u][2]; s1.y = acc[u][3];
                *(ulonglong2*)(pl + np * 16 + cg4)     = s0;
                *(ulonglong2*)(pl + np * 16 + cg4 + 2) = s1;
            }
        }
        __syncthreads();

        // reduce 16 planes + xw
        if (tid < 256) {
            ull s = 0ULL;
#pragma unroll
            for (int p = 0; p < 16; p++) add2(s, ap[p * APS + tid]);
            float lo, hi;
            unpack2(lo, hi, s);
            af[rc * 34 + 2 * rnp]     = lo + xw0;
            af[rc * 34 + 2 * rnp + 1] = hi + xw1;
        }
        __syncthreads();

        // gates
        if (tid < 128) {
            int jj = tid >> 5, n = tid & 31;
            float ai  = af[(jj)      * 34 + n];
            float afv = af[(4 + jj)  * 34 + n];
            float ao  = af[(8 + jj)  * 34 + n];
            float ag  = af[(12 + jj) * 34 + n];
            float ig = 1.f / (1.f + expf(-ai));
            float fg = 1.f / (1.f + expf(-afv));
            float og = 1.f / (1.f + expf(-ao));
            float gg = tanhf(ag);
            float cn = fg * cs[tid] + ig * gg;
            cs[tid] = cn;
            float hn = og * tanhf(cn);
            g_hbuf[(t + 1) & 1][j0 + jj][n] = hn;
            out[((size_t)n * T_ + t) * H_ + j0 + jj] = hn;
        }
        gridbar(b, step); step++;
    }
}

// ---------------- launch ----------------------------------------------------------
extern "C" void kernel_launch(void* const* d_in, const int* in_sizes, int n_in,
                              void* d_out, int out_size)
{
    const float* x    = (const float*)d_in[0];
    const float* h0   = (const float*)d_in[1];
    const float* Wx   = (const float*)d_in[2];
    const float* Wh   = (const float*)d_in[3];
    const float* bias = (const float*)d_in[4];
    float* out = (float*)d_out;

    reset_barrier_kernel<<<1, 32>>>();

    dim3 g1(G4 / 128, (N_ * T_) / 128);
    gemm_xw_kernel<<<g1, 256>>>(x, Wx, bias);

    const int shmem = (512 * 16 + 512 * 32 + 16 * APS * 2 + 16 * 34 + 128) * (int)sizeof(float);
    cudaFuncSetAttribute(lstm_rec_kernel, cudaFuncAttributeMaxDynamicSharedMemorySize, shmem);
    lstm_rec_kernel<<<NB, NTH, shmem>>>(h0, Wh, out);
}

// round 6
// speedup vs baseline: 1.0527x; 1.0213x over previous
#include <cuda_runtime.h>
#include <cstdint>
#include <math.h>

#define N_  32
#define T_  1024
#define D_  512
#define H_  512
#define G4  2048

#define NB   128
#define NTH  512
#define APW  288     // ap row stride factor basis: index np*18+c, plane stride APW ull

typedef unsigned long long ull;

__device__ __forceinline__ void fma2(ull& d, const ull a, const ull b) {
    asm("fma.rn.f32x2 %0, %1, %2, %0;" : "+l"(d) : "l"(a), "l"(b));
}
__device__ __forceinline__ void add2(ull& d, const ull a) {
    asm("add.rn.f32x2 %0, %0, %1;" : "+l"(d) : "l"(a));
}
__device__ __forceinline__ ull bcast2(float x) {
    ull r; asm("mov.b64 %0, {%1, %1};" : "=l"(r) : "f"(x)); return r;
}
__device__ __forceinline__ void unpack2(float& lo, float& hi, ull a) {
    asm("mov.b64 {%0, %1}, %2;" : "=f"(lo), "=f"(hi) : "l"(a));
}
__device__ __forceinline__ float fsig(float x) { return 1.f / (1.f + __expf(-x)); }
__device__ __forceinline__ float ftanh(float x) { return 2.f / (1.f + __expf(-2.f * x)) - 1.f; }

// ---------------- device scratch -------------------------------------------------
__device__ float g_xw[(size_t)N_ * T_ * G4];   // x@Wx + b, [n][t][2048]
__device__ float g_hbuf[2][H_][N_];            // double-buffered h, [k][n]
__device__ unsigned int g_grp[16 * 64];
__device__ unsigned int g_root = 0;
__device__ volatile unsigned int g_gen = 0;

__global__ void reset_barrier_kernel()
{
    int i = threadIdx.x;
    if (i < 16) g_grp[i * 64] = 0u;
    if (i == 16) g_root = 0u;
    if (i == 17) g_gen = 0u;
}

// ---------------- Phase 1: xw = x @ Wx + b (unchanged, proven) --------------------
__global__ __launch_bounds__(256, 2) void gemm_xw_kernel(const float* __restrict__ x,
                                                         const float* __restrict__ Wx,
                                                         const float* __restrict__ bias)
{
    __shared__ float As[8][128];
    __shared__ float Bs[8][128];
    const int tid = threadIdx.x;
    const int bm = blockIdx.y, bn = blockIdx.x;
    const int tx = tid & 15, ty = tid >> 4;
    const int a_row = tid >> 1, a_k = (tid & 1) << 2;
    const int b_row = tid >> 5, b_col = (tid & 31) << 2;

    const float* xA = x + (size_t)(bm * 128 + a_row) * D_ + a_k;
    const float* wB = Wx + (size_t)b_row * G4 + bn * 128 + b_col;

    ull accp[8][4];
#pragma unroll
    for (int i = 0; i < 8; i++)
#pragma unroll
        for (int j = 0; j < 4; j++) accp[i][j] = 0ULL;

    for (int k0 = 0; k0 < D_; k0 += 8) {
        float4 av = *(const float4*)(xA + k0);
        float4 bv = *(const float4*)(wB + (size_t)k0 * G4);
        __syncthreads();
        As[a_k + 0][a_row] = av.x;
        As[a_k + 1][a_row] = av.y;
        As[a_k + 2][a_row] = av.z;
        As[a_k + 3][a_row] = av.w;
        *(float4*)&Bs[b_row][b_col] = bv;
        __syncthreads();
#pragma unroll
        for (int kk = 0; kk < 8; kk++) {
            float a0[8];
            *(float4*)(a0)     = *(const float4*)&As[kk][ty * 8];
            *(float4*)(a0 + 4) = *(const float4*)&As[kk][ty * 8 + 4];
            ulonglong2 q0 = *(const ulonglong2*)&Bs[kk][tx * 8];
            ulonglong2 q1 = *(const ulonglong2*)&Bs[kk][tx * 8 + 4];
            ull b2[4] = {q0.x, q0.y, q1.x, q1.y};
            ull a2[8];
#pragma unroll
            for (int i = 0; i < 8; i++) a2[i] = bcast2(a0[i]);
#pragma unroll
            for (int i = 0; i < 8; i++)
#pragma unroll
                for (int j = 0; j < 4; j++)
                    fma2(accp[i][j], a2[i], b2[j]);
        }
    }

    ulonglong2 bq0 = *(const ulonglong2*)(bias + bn * 128 + tx * 8);
    ulonglong2 bq1 = *(const ulonglong2*)(bias + bn * 128 + tx * 8 + 4);
    ull bb2[4] = {bq0.x, bq0.y, bq1.x, bq1.y};
#pragma unroll
    for (int i = 0; i < 8; i++) {
#pragma unroll
        for (int j = 0; j < 4; j++) add2(accp[i][j], bb2[j]);
        size_t row = (size_t)(bm * 128 + ty * 8 + i);
        ulonglong2 s0, s1;
        s0.x = accp[i][0]; s0.y = accp[i][1];
        s1.x = accp[i][2]; s1.y = accp[i][3];
        *(ulonglong2*)(g_xw + row * G4 + bn * 128 + tx * 8)     = s0;
        *(ulonglong2*)(g_xw + row * G4 + bn * 128 + tx * 8 + 4) = s1;
    }
}

// ---------------- Phase 2 --------------------------------------------------------
// release fence kept (cumulative); acquire fence dropped (all cross-CTA reads __ldcg)
__device__ __forceinline__ void gridbar(int b, unsigned s)
{
    __syncthreads();
    if (threadIdx.x == 0) {
        __threadfence();
        unsigned old = atomicAdd(&g_grp[(b >> 3) * 64], 1u);
        if (old == 8u * s - 1u) {
            unsigned r = atomicAdd(&g_root, 1u);
            if (r == 16u * s - 1u) { __threadfence(); g_gen = s; }
        }
        while (g_gen < s) { }
    }
    __syncthreads();
}

extern __shared__ float smem_dyn[];

__global__ __launch_bounds__(NTH, 1) void lstm_rec_kernel(const float* __restrict__ h0,
                                                          const float* __restrict__ Wh,
                                                          float* __restrict__ out)
{
    // smem: ws[512][16] | hs[512][32] | ap ull[16][APW] | cs[128]
    float* ws = smem_dyn;                     // 8192 floats
    float* hs = ws + 512 * 16;                // 16384 floats
    ull*   ap = (ull*)(hs + 512 * 32);        // 16*APW ull
    float* cs = (float*)(ap + 16 * APW);      // 128 floats

    const int b   = blockIdx.x;
    const int tid = threadIdx.x;
    const int j0  = b * 4;

    // weights: ws[k][c], c = gate*4+jj
    for (int idx = tid; idx < 512 * 16; idx += NTH) {
        int k = idx >> 4, c = idx & 15;
        ws[idx] = Wh[(size_t)k * G4 + (c >> 2) * H_ + j0 + (c & 3)];
    }
    if (tid < 128) {
        cs[tid] = 0.f;
        int jj = tid >> 5, n = tid & 31;
        g_hbuf[0][j0 + jj][n] = h0[(size_t)n * H_ + j0 + jj];
    }
    unsigned step = 1;
    gridbar(b, step); step++;

    // GEMM mapping
    const int w    = tid >> 5;                 // warp, k in [w*32, w*32+32)
    const int lane = tid & 31;
    const int kg   = lane >> 4;
    const int pos  = lane & 15;
    const int n0   = (pos & 3) * 8;
    const int cg4  = (pos >> 2) * 4;
    const int kbase = w * 32 + kg * 16;

    // reduce/gates ids (tid < 64): np = tid>>2, jj = tid&3
    const int np = tid >> 2, jj = tid & 3;

    // xw prefetch regs for step t (loaded one step ahead), + deferred out values
    float xwr[2][4];
    float hn0 = 0.f, hn1 = 0.f;
    if (tid < 64) {
#pragma unroll
        for (int r = 0; r < 2; r++)
#pragma unroll
            for (int g = 0; g < 4; g++)
                xwr[r][g] = __ldcg(g_xw + ((size_t)(2 * np + r) * T_ + 0) * G4 + g * H_ + j0 + jj);
    }

    for (int t = 0; t < T_; t++) {
        // deferred out write for step t-1 (drained by a later fence, off critical path)
        if (t > 0 && tid < 64) {
            out[((size_t)(2 * np)     * T_ + (t - 1)) * H_ + j0 + jj] = hn0;
            out[((size_t)(2 * np + 1) * T_ + (t - 1)) * H_ + j0 + jj] = hn1;
        }

        // stage OWN k-slice: warp w stages rows [w*32, w*32+32)  (warp-local only)
        const float* hb = &g_hbuf[t & 1][0][0];
        {
            int chunk = (lane & 7) * 4;
#pragma unroll
            for (int rr = 0; rr < 8; rr++) {
                int row = w * 32 + rr * 4 + (lane >> 3);
                float4 v = __ldcg((const float4*)(hb + row * 32 + chunk));
                *(float4*)(hs + row * 32 + chunk) = v;
            }
        }
        __syncwarp();

        // GEMM: acc[np 4][c 4], n-packed f32x2
        ull acc[4][4];
#pragma unroll
        for (int u = 0; u < 4; u++)
#pragma unroll
            for (int c = 0; c < 4; c++) acc[u][c] = 0ULL;

#pragma unroll
        for (int i = 0; i < 16; i++) {
            int k = kbase + i;
            const float* hr = hs + k * 32 + n0;
            ulonglong2 hA = *(const ulonglong2*)hr;
            ulonglong2 hB = *(const ulonglong2*)(hr + 4);
            ull hv[4] = {hA.x, hA.y, hB.x, hB.y};
            float4 wf = *(const float4*)(ws + k * 16 + cg4);
            ull wb[4] = {bcast2(wf.x), bcast2(wf.y), bcast2(wf.z), bcast2(wf.w)};
#pragma unroll
            for (int u = 0; u < 4; u++)
#pragma unroll
                for (int c = 0; c < 4; c++)
                    fma2(acc[u][c], hv[u], wb[c]);
        }
#pragma unroll
        for (int u = 0; u < 4; u++)
#pragma unroll
            for (int c = 0; c < 4; c++) {
                ull o = __shfl_xor_sync(0xFFFFFFFFu, acc[u][c], 16);
                add2(acc[u][c], o);
            }
        if (kg == 0) {
            ull* pl = ap + w * APW;
#pragma unroll
            for (int u = 0; u < 4; u++) {
                int npw = (n0 >> 1) + u;
                ulonglong2 s0, s1;
                s0.x = acc[u][0]; s0.y = acc[u][1];
                s1.x = acc[u][2]; s1.y = acc[u][3];
                *(ulonglong2*)(pl + npw * 18 + cg4)     = s0;
                *(ulonglong2*)(pl + npw * 18 + cg4 + 2) = s1;
            }
        }
        __syncthreads();

        // fused reduce + gates (64 threads: np x jj)
        if (tid < 64) {
            ull s0 = 0ULL, s1 = 0ULL, s2 = 0ULL, s3 = 0ULL;
            const ull* base = ap + np * 18 + jj;
#pragma unroll
            for (int p = 0; p < 16; p++) {
                const ull* pl = base + p * APW;
                add2(s0, pl[0]);
                add2(s1, pl[4]);
                add2(s2, pl[8]);
                add2(s3, pl[12]);
            }
            float a0l, a0h, a1l, a1h, a2l, a2h, a3l, a3h;
            unpack2(a0l, a0h, s0);
            unpack2(a1l, a1h, s1);
            unpack2(a2l, a2h, s2);
            unpack2(a3l, a3h, s3);
            // n = 2np
            {
                float ig = fsig(a0l + xwr[0][0]);
                float fg = fsig(a1l + xwr[0][1]);
                float og = fsig(a2l + xwr[0][2]);
                float gg = ftanh(a3l + xwr[0][3]);
                float cn = fg * cs[2 * np * 4 + jj] + ig * gg;
                cs[2 * np * 4 + jj] = cn;
                hn0 = og * ftanh(cn);
                g_hbuf[(t + 1) & 1][j0 + jj][2 * np] = hn0;
            }
            // n = 2np+1
            {
                float ig = fsig(a0h + xwr[1][0]);
                float fg = fsig(a1h + xwr[1][1]);
                float og = fsig(a2h + xwr[1][2]);
                float gg = ftanh(a3h + xwr[1][3]);
                float cn = fg * cs[(2 * np + 1) * 4 + jj] + ig * gg;
                cs[(2 * np + 1) * 4 + jj] = cn;
                hn1 = og * ftanh(cn);
                g_hbuf[(t + 1) & 1][j0 + jj][2 * np + 1] = hn1;
            }
            // prefetch xw for step t+1 (off critical path, survives barrier)
            if (t + 1 < T_) {
#pragma unroll
                for (int r = 0; r < 2; r++)
#pragma unroll
                    for (int g = 0; g < 4; g++)
                        xwr[r][g] = __ldcg(g_xw + ((size_t)(2 * np + r) * T_ + (t + 1)) * G4 + g * H_ + j0 + jj);
            }
        }
        gridbar(b, step); step++;
    }

    // final deferred out write
    if (tid < 64) {
        out[((size_t)(2 * np)     * T_ + (T_ - 1)) * H_ + j0 + jj] = hn0;
        out[((size_t)(2 * np + 1) * T_ + (T_ - 1)) * H_ + j0 + jj] = hn1;
    }
}

// ---------------- launch ----------------------------------------------------------
extern "C" void kernel_launch(void* const* d_in, const int* in_sizes, int n_in,
                              void* d_out, int out_size)
{
    const float* x    = (const float*)d_in[0];
    const float* h0   = (const float*)d_in[1];
    const float* Wx   = (const float*)d_in[2];
    const float* Wh   = (const float*)d_in[3];
    const float* bias = (const float*)d_in[4];
    float* out = (float*)d_out;

    reset_barrier_kernel<<<1, 32>>>();

    dim3 g1(G4 / 128, (N_ * T_) / 128);
    gemm_xw_kernel<<<g1, 256>>>(x, Wx, bias);

    const int shmem = (512 * 16 + 512 * 32) * 4 + 16 * APW * 8 + 128 * 4;
    cudaFuncSetAttribute(lstm_rec_kernel, cudaFuncAttributeMaxDynamicSharedMemorySize, shmem);
    lstm_rec_kernel<<<NB, NTH, shmem>>>(h0, Wh, out);
}